// round 1
// baseline (speedup 1.0000x reference)
#include <cuda_runtime.h>
#include <cstring>

#define LREF  1024
#define KW    5
#define FEA   1028
#define MEMD  50
#define DATED 32
#define MAXB  32768

// scratch (allocation-free rule: __device__ globals)
__device__ float g_att[MAXB * MEMD];      // (B,50)
__device__ float g_Wconv[MEMD * LREF];    // (50,1024)

typedef unsigned long long ull;

__device__ __forceinline__ ull fma2(ull a, ull b, ull c) {
    ull d;
    asm("fma.rn.f32x2 %0, %1, %2, %3;" : "=l"(d) : "l"(a), "l"(b), "l"(c));
    return d;
}
__device__ __forceinline__ float2 ull_as_f2(ull u) { float2 v; memcpy(&v, &u, 8); return v; }
__device__ __forceinline__ ull f2_as_ull(float2 v) { ull u; memcpy(&u, &v, 8); return u; }

// ---------------------------------------------------------------------------
// k0: Wconv[m][i] = sum_k mem_W[m][i+k] * convt_w[K-1-k]   (conv folded into GEMM B matrix)
// ---------------------------------------------------------------------------
__global__ void k_wconv(const float* __restrict__ mem_W, const float* __restrict__ convt_w) {
    int i = blockIdx.x * blockDim.x + threadIdx.x;
    if (i >= MEMD * LREF) return;
    int m = i / LREF, c = i % LREF;
    float w0 = convt_w[4], w1 = convt_w[3], w2 = convt_w[2], w3 = convt_w[1], w4 = convt_w[0];
    const float* p = mem_W + m * FEA + c;
    float s = p[0]*w0 + p[1]*w1 + p[2]*w2 + p[3]*w3 + p[4]*w4;
    g_Wconv[i] = s;
}

// ---------------------------------------------------------------------------
// k1: att = renorm(shrink(softmax(date_vector @ date_W.T)))   one thread per row
// ---------------------------------------------------------------------------
__global__ __launch_bounds__(256) void k_att(const float* __restrict__ dv,
                                             const float* __restrict__ dW) {
    __shared__ float s_dv[256][DATED + 1];
    __shared__ float s_dW[MEMD][DATED];
    __shared__ float s_out[256][MEMD + 1];

    int t = threadIdx.x;
    int base = blockIdx.x * 256;

    for (int i = t; i < MEMD * DATED; i += 256) s_dW[i / DATED][i % DATED] = dW[i];
    for (int i = t; i < 256 * DATED; i += 256)
        s_dv[i / DATED][i % DATED] = dv[(size_t)base * DATED + i];
    __syncthreads();

    float sc[MEMD];
    float mx = -1e30f;
    #pragma unroll
    for (int m = 0; m < MEMD; m++) {
        float s = 0.f;
        #pragma unroll
        for (int d = 0; d < DATED; d++) s += s_dv[t][d] * s_dW[m][d];
        sc[m] = s;
        mx = fmaxf(mx, s);
    }
    float se = 0.f;
    #pragma unroll
    for (int m = 0; m < MEMD; m++) { float e = __expf(sc[m] - mx); sc[m] = e; se += e; }
    float inv = 1.f / se;
    float s2 = 0.f;
    #pragma unroll
    for (int m = 0; m < MEMD; m++) {
        float a = sc[m] * inv;
        float d = a - 0.0025f;
        float v = fmaxf(d, 0.f) * a / (fabsf(d) + 1e-12f);
        sc[m] = v;
        s2 += fabsf(v);
    }
    float inv2 = 1.f / (s2 + 1e-12f);
    #pragma unroll
    for (int m = 0; m < MEMD; m++) s_out[t][m] = sc[m] * inv2;
    __syncthreads();

    // coalesced write-out
    for (int i = t; i < 256 * MEMD; i += 256) {
        int r = i / MEMD, m = i % MEMD;
        g_att[(size_t)base * MEMD + i] = s_out[r][m];
    }
}

// ---------------------------------------------------------------------------
// k2: fused main. Block = 64 rows.
//   phase A: weight/bias = f(x row dots) warp-cooperative, coalesced
//   phase B: st = att @ Wconv, FFMA2, fused epilogue st*weight+bias
// out layout: [st (B*L)] [weight (B)] [bias (B)]
// ---------------------------------------------------------------------------
#define BM 64
#define BN 128
#define TM 8

__global__ __launch_bounds__(256) void k_main(const float* __restrict__ x,
                                              const float* __restrict__ fcw,
                                              const float* __restrict__ fcwb,
                                              const float* __restrict__ fcb,
                                              const float* __restrict__ fcbb,
                                              float* __restrict__ out, int Bn) {
    __shared__ float  s_fcw[LREF];
    __shared__ float  s_fcb[LREF];
    __shared__ float2 s_att2[BM * MEMD];   // packed {a,a}
    __shared__ float  s_W[MEMD][BN];
    __shared__ float  s_wt[BM];
    __shared__ float  s_bs[BM];

    int t = threadIdx.x;
    int warp = t >> 5, lane = t & 31;
    int rowBase = blockIdx.x * BM;

    for (int i = t; i < LREF; i += 256) { s_fcw[i] = fcw[i]; s_fcb[i] = fcb[i]; }
    // att tile (coalesced), packed to {a,a}
    for (int i = t; i < BM * MEMD; i += 256) {
        float v = g_att[(size_t)rowBase * MEMD + i];
        s_att2[i] = make_float2(v, v);
    }
    __syncthreads();

    // ---- phase A: per-row dots with fcw/fcb ----
    float fwb = fcwb[0], fbb = fcbb[0];
    #pragma unroll
    for (int rr = 0; rr < BM / 8; rr++) {
        int r = warp * (BM / 8) + rr;
        const float4* xr = (const float4*)(x + (size_t)(rowBase + r) * LREF);
        const float4* fw4 = (const float4*)s_fcw;
        const float4* fb4 = (const float4*)s_fcb;
        float dw = 0.f, db = 0.f;
        #pragma unroll
        for (int j = 0; j < LREF / 4 / 32; j++) {
            float4 v = xr[lane + 32 * j];
            float4 a = fw4[lane + 32 * j];
            float4 b = fb4[lane + 32 * j];
            dw += v.x * a.x + v.y * a.y + v.z * a.z + v.w * a.w;
            db += v.x * b.x + v.y * b.y + v.z * b.z + v.w * b.w;
        }
        #pragma unroll
        for (int o = 16; o; o >>= 1) {
            dw += __shfl_xor_sync(0xffffffffu, dw, o);
            db += __shfl_xor_sync(0xffffffffu, db, o);
        }
        if (lane == 0) {
            float wt = tanhf(dw + fwb) * 0.5f + 1.0f;
            float bs = tanhf(db + fbb) * 0.5f;
            s_wt[r] = wt;
            s_bs[r] = bs;
            out[(size_t)Bn * LREF + rowBase + r]      = wt;
            out[(size_t)Bn * LREF + Bn + rowBase + r] = bs;
        }
    }
    __syncthreads();

    // ---- phase B: GEMM (64 x 1024 x 50) ----
    int tx = t & 31, ty = t >> 5;               // tx: 32 col groups, ty: 8 row groups
    const ull* attp = (const ull*)s_att2;

    for (int cb = 0; cb < LREF / BN; cb++) {
        for (int i = t; i < MEMD * BN; i += 256) {
            int k = i / BN, c = i % BN;
            s_W[k][c] = g_Wconv[k * LREF + cb * BN + c];
        }
        __syncthreads();

        ull acc[TM][2];
        #pragma unroll
        for (int r = 0; r < TM; r++) { acc[r][0] = 0ull; acc[r][1] = 0ull; }

        #pragma unroll 2
        for (int k = 0; k < MEMD; k++) {
            float4 wv = *(const float4*)&s_W[k][tx * 4];
            ull w01 = f2_as_ull(make_float2(wv.x, wv.y));
            ull w23 = f2_as_ull(make_float2(wv.z, wv.w));
            #pragma unroll
            for (int r = 0; r < TM; r++) {
                ull a2 = attp[(ty * TM + r) * MEMD + k];
                acc[r][0] = fma2(a2, w01, acc[r][0]);
                acc[r][1] = fma2(a2, w23, acc[r][1]);
            }
        }

        #pragma unroll
        for (int r = 0; r < TM; r++) {
            int row = rowBase + ty * TM + r;
            float wt = s_wt[ty * TM + r];
            float bs = s_bs[ty * TM + r];
            float2 p0 = ull_as_f2(acc[r][0]);
            float2 p1 = ull_as_f2(acc[r][1]);
            float4 o;
            o.x = p0.x * wt + bs;
            o.y = p0.y * wt + bs;
            o.z = p1.x * wt + bs;
            o.w = p1.y * wt + bs;
            *(float4*)&out[(size_t)row * LREF + cb * BN + tx * 4] = o;
        }
        __syncthreads();
    }
}

// ---------------------------------------------------------------------------
extern "C" void kernel_launch(void* const* d_in, const int* in_sizes, int n_in,
                              void* d_out, int out_size) {
    const float* x    = (const float*)d_in[0];
    const float* dv   = (const float*)d_in[1];
    // d_in[2] = conv_w  (dead code in reference)
    const float* ctw  = (const float*)d_in[3];
    const float* memW = (const float*)d_in[4];
    const float* dW   = (const float*)d_in[5];
    const float* fcw  = (const float*)d_in[6];
    const float* fcwb = (const float*)d_in[7];
    const float* fcb  = (const float*)d_in[8];
    const float* fcbb = (const float*)d_in[9];
    float* out = (float*)d_out;

    int Bn = in_sizes[0] / LREF;   // 32768

    k_wconv<<<(MEMD * LREF + 255) / 256, 256>>>(memW, ctw);
    k_att<<<Bn / 256, 256>>>(dv, dW);
    k_main<<<Bn / BM, 256>>>(x, fcw, fcwb, fcb, fcbb, out, Bn);
}

// round 5
// speedup vs baseline: 1.5607x; 1.5607x over previous
#include <cuda_runtime.h>
#include <cuda_bf16.h>
#include <cstdint>

#define LREF  1024
#define KW    5
#define FEA   1028
#define MEMD  50
#define KPAD  64
#define DATED 32
#define MAXB  32768

// ------------------- device scratch (allocation-free rule) -------------------
__device__ __nv_bfloat16 g_atth[MAXB * KPAD];   // att hi  [row][k] padded
__device__ __nv_bfloat16 g_attl[MAXB * KPAD];   // att lo
__device__ __nv_bfloat16 g_Bh[LREF * KPAD];     // Wfold^T hi [col][k]
__device__ __nv_bfloat16 g_Bl[LREF * KPAD];     // Wfold^T lo

// ------------------- helpers -------------------
__device__ __forceinline__ uint32_t smem_u32(const void* p) {
    uint32_t a;
    asm("{ .reg .u64 t; cvta.to.shared.u64 t, %1; cvt.u32.u64 %0, t; }" : "=r"(a) : "l"(p));
    return a;
}
__device__ __forceinline__ void ldsm_x4(uint32_t* r, uint32_t a) {
    asm volatile("ldmatrix.sync.aligned.m8n8.x4.shared.b16 {%0,%1,%2,%3}, [%4];"
                 : "=r"(r[0]), "=r"(r[1]), "=r"(r[2]), "=r"(r[3]) : "r"(a));
}
__device__ __forceinline__ void ldsm_x2(uint32_t* r, uint32_t a) {
    asm volatile("ldmatrix.sync.aligned.m8n8.x2.shared.b16 {%0,%1}, [%2];"
                 : "=r"(r[0]), "=r"(r[1]) : "r"(a));
}
__device__ __forceinline__ void mma_bf16(float* d, const uint32_t* a, const uint32_t* b) {
    asm volatile(
        "mma.sync.aligned.m16n8k16.row.col.f32.bf16.bf16.f32 "
        "{%0,%1,%2,%3}, {%4,%5,%6,%7}, {%8,%9}, {%0,%1,%2,%3};"
        : "+f"(d[0]), "+f"(d[1]), "+f"(d[2]), "+f"(d[3])
        : "r"(a[0]), "r"(a[1]), "r"(a[2]), "r"(a[3]), "r"(b[0]), "r"(b[1]));
}

// ---------------------------------------------------------------------------
// k0: fold convt into mem_W, transpose -> [col][k], bf16 hi/lo, pad K 50->64
// ---------------------------------------------------------------------------
__global__ void k_wconv(const float* __restrict__ mem_W, const float* __restrict__ convt_w) {
    int i = blockIdx.x * blockDim.x + threadIdx.x;
    if (i >= LREF * KPAD) return;
    int c = i >> 6, k = i & 63;
    float s = 0.f;
    if (k < MEMD) {
        float w0 = convt_w[4], w1 = convt_w[3], w2 = convt_w[2], w3 = convt_w[1], w4 = convt_w[0];
        const float* p = mem_W + k * FEA + c;
        s = p[0]*w0 + p[1]*w1 + p[2]*w2 + p[3]*w3 + p[4]*w4;
    }
    __nv_bfloat16 h = __float2bfloat16_rn(s);
    __nv_bfloat16 l = __float2bfloat16_rn(s - __bfloat162float(h));
    g_Bh[i] = h;
    g_Bl[i] = l;
}

// ---------------------------------------------------------------------------
// k1: att = renorm(shrink(softmax(dv @ dW.T))), emit bf16 hi/lo padded K=64
// ---------------------------------------------------------------------------
__global__ __launch_bounds__(256) void k_att(const float* __restrict__ dv,
                                             const float* __restrict__ dW) {
    __shared__ float s_dv[256][DATED + 1];
    __shared__ float s_dW[MEMD][DATED];
    __shared__ float s_out[256][MEMD + 1];

    int t = threadIdx.x;
    int base = blockIdx.x * 256;

    for (int i = t; i < MEMD * DATED; i += 256) s_dW[i / DATED][i % DATED] = dW[i];
    for (int i = t; i < 256 * DATED; i += 256)
        s_dv[i / DATED][i % DATED] = dv[(size_t)base * DATED + i];
    __syncthreads();

    float sc[MEMD];
    float mx = -1e30f;
    #pragma unroll
    for (int m = 0; m < MEMD; m++) {
        float s = 0.f;
        #pragma unroll
        for (int d = 0; d < DATED; d++) s += s_dv[t][d] * s_dW[m][d];
        sc[m] = s;
        mx = fmaxf(mx, s);
    }
    float se = 0.f;
    #pragma unroll
    for (int m = 0; m < MEMD; m++) { float e = __expf(sc[m] - mx); sc[m] = e; se += e; }
    float inv = 1.f / se;
    float s2 = 0.f;
    #pragma unroll
    for (int m = 0; m < MEMD; m++) {
        float a = sc[m] * inv;
        float d = a - 0.0025f;
        float v = fmaxf(d, 0.f) * a / (fabsf(d) + 1e-12f);
        sc[m] = v;
        s2 += fabsf(v);
    }
    float inv2 = 1.f / (s2 + 1e-12f);
    #pragma unroll
    for (int m = 0; m < MEMD; m++) s_out[t][m] = sc[m] * inv2;
    __syncthreads();

    // write bf16 hi/lo, K padded to 64, coalesced
    for (int i = t; i < 256 * KPAD; i += 256) {
        int r = i >> 6, k = i & 63;
        float a = (k < MEMD) ? s_out[r][k] : 0.f;
        __nv_bfloat16 h = __float2bfloat16_rn(a);
        __nv_bfloat16 l = __float2bfloat16_rn(a - __bfloat162float(h));
        size_t gi = (size_t)base * KPAD + i;
        g_atth[gi] = h;
        g_attl[gi] = l;
    }
}

// ---------------------------------------------------------------------------
// k2: fused main. CTA = 128 rows, 256 threads, 8 warps (each m16 stripe).
//     GEMM via mma.sync bf16 3-term split; fused tanh gates + epilogue.
// ---------------------------------------------------------------------------
#define ASTRIDE 144          // 64 bf16 = 128B padded to 144B (ldmatrix conflict-free)
#define OFF_FCW 0
#define OFF_FCB 4096
#define OFF_WT  8192
#define OFF_BS  8704
#define OFF_AH  9216
#define OFF_AL  (OFF_AH + 128 * ASTRIDE)
#define OFF_BH  (OFF_AL + 128 * ASTRIDE)
#define OFF_BL  (OFF_BH + 128 * ASTRIDE)
#define SMEM_SZ (OFF_BL + 128 * ASTRIDE)

__global__ __launch_bounds__(256, 2) void k_main(const float* __restrict__ x,
                                                 const float* __restrict__ fcw,
                                                 const float* __restrict__ fcwb,
                                                 const float* __restrict__ fcb,
                                                 const float* __restrict__ fcbb,
                                                 float* __restrict__ out, int Bn) {
    extern __shared__ char smem[];
    const uint32_t sb = smem_u32(smem);
    const int t = threadIdx.x;
    const int warp = t >> 5, lane = t & 31;
    const int rowBase = blockIdx.x * 128;

    float* s_fcw = (float*)(smem + OFF_FCW);
    float* s_fcb = (float*)(smem + OFF_FCB);
    float* s_wt  = (float*)(smem + OFF_WT);
    float* s_bs  = (float*)(smem + OFF_BS);

    // ---- stage fc weights + A (att) tiles ----
    for (int i = t; i < LREF / 4; i += 256) {
        ((float4*)s_fcw)[i] = ((const float4*)fcw)[i];
        ((float4*)s_fcb)[i] = ((const float4*)fcb)[i];
    }
    for (int i = t; i < 2048; i += 256) {
        int term = i >> 10, rem = i & 1023, r = rem >> 3, ch = rem & 7;
        const __nv_bfloat16* src = (term ? g_attl : g_atth) + (size_t)(rowBase + r) * KPAD + ch * 8;
        *(uint4*)(smem + OFF_AH + term * (128 * ASTRIDE) + r * ASTRIDE + ch * 16) =
            *(const uint4*)src;
    }
    __syncthreads();

    // ---- A fragments into registers (once) ----
    uint32_t ah[4][4], al[4][4];
    {
        uint32_t aoff = (uint32_t)((warp * 16 + (lane & 15)) * ASTRIDE + (lane >> 4) * 16);
        #pragma unroll
        for (int ks = 0; ks < 4; ks++) {
            ldsm_x4(ah[ks], sb + OFF_AH + aoff + ks * 32);
            ldsm_x4(al[ks], sb + OFF_AL + aoff + ks * 32);
        }
    }

    // ---- phase A: per-row tanh gates (8 warps x 16 rows) ----
    {
        float fwb = fcwb[0], fbb = fcbb[0];
        for (int rr = 0; rr < 16; rr++) {
            int r = warp * 16 + rr;
            const float4* xr  = (const float4*)(x + (size_t)(rowBase + r) * LREF);
            const float4* fw4 = (const float4*)s_fcw;
            const float4* fb4 = (const float4*)s_fcb;
            float dw = 0.f, db = 0.f;
            #pragma unroll
            for (int j = 0; j < 8; j++) {
                float4 v = xr[lane + 32 * j];
                float4 a = fw4[lane + 32 * j];
                float4 b = fb4[lane + 32 * j];
                dw += v.x*a.x + v.y*a.y + v.z*a.z + v.w*a.w;
                db += v.x*b.x + v.y*b.y + v.z*b.z + v.w*b.w;
            }
            #pragma unroll
            for (int o = 16; o; o >>= 1) {
                dw += __shfl_xor_sync(0xffffffffu, dw, o);
                db += __shfl_xor_sync(0xffffffffu, db, o);
            }
            if (lane == 0) {
                float wt = tanhf(dw + fwb) * 0.5f + 1.0f;
                float bs = tanhf(db + fbb) * 0.5f;
                s_wt[r] = wt;
                s_bs[r] = bs;
                out[(size_t)Bn * LREF + rowBase + r]      = wt;
                out[(size_t)Bn * LREF + Bn + rowBase + r] = bs;
            }
        }
    }
    __syncthreads();

    // per-thread epilogue coords
    const int grp = lane >> 2, qc = lane & 3;
    const float wt0 = s_wt[warp * 16 + grp],     bs0 = s_bs[warp * 16 + grp];
    const float wt1 = s_wt[warp * 16 + grp + 8], bs1 = s_bs[warp * 16 + grp + 8];
    const uint32_t bfrag_off = (uint32_t)((lane & 7) * ASTRIDE + ((lane >> 3) & 1) * 16);

    // ---- GEMM over 8 col-blocks of 128 ----
    for (int cb = 0; cb < 8; cb++) {
        // stage B tile (hi/lo) for cols [cb*128, cb*128+128)
        for (int i = t; i < 2048; i += 256) {
            int term = i >> 10, rem = i & 1023, r = rem >> 3, ch = rem & 7;
            const __nv_bfloat16* src =
                (term ? g_Bl : g_Bh) + (size_t)(cb * 128 + r) * KPAD + ch * 8;
            *(uint4*)(smem + OFF_BH + term * (128 * ASTRIDE) + r * ASTRIDE + ch * 16) =
                *(const uint4*)src;
        }
        __syncthreads();

        float acc[16][4];
        #pragma unroll
        for (int nt = 0; nt < 16; nt++) {
            acc[nt][0] = 0.f; acc[nt][1] = 0.f; acc[nt][2] = 0.f; acc[nt][3] = 0.f;
        }

        #pragma unroll
        for (int ks = 0; ks < 4; ks++) {
            #pragma unroll
            for (int nt = 0; nt < 16; nt++) {
                uint32_t bh[2], bl[2];
                uint32_t boff = bfrag_off + (uint32_t)(nt * 8 * ASTRIDE + ks * 32);
                ldsm_x2(bh, sb + OFF_BH + boff);
                ldsm_x2(bl, sb + OFF_BL + boff);
                mma_bf16(acc[nt], ah[ks], bh);
                mma_bf16(acc[nt], al[ks], bh);
                mma_bf16(acc[nt], ah[ks], bl);
            }
        }

        // fused epilogue: out = acc*wt + bs, sector-aligned float2 stores
        {
            size_t r0 = (size_t)(rowBase + warp * 16 + grp) * LREF;
            size_t r1 = r0 + 8 * LREF;
            int colBase = cb * 128 + qc * 2;
            #pragma unroll
            for (int nt = 0; nt < 16; nt++) {
                int col = colBase + nt * 8;
                float2 o0 = make_float2(acc[nt][0] * wt0 + bs0, acc[nt][1] * wt0 + bs0);
                float2 o1 = make_float2(acc[nt][2] * wt1 + bs1, acc[nt][3] * wt1 + bs1);
                *(float2*)&out[r0 + col] = o0;
                *(float2*)&out[r1 + col] = o1;
            }
        }
        __syncthreads();   // before next B staging overwrites
    }
}

// ---------------------------------------------------------------------------
extern "C" void kernel_launch(void* const* d_in, const int* in_sizes, int n_in,
                              void* d_out, int out_size) {
    const float* x    = (const float*)d_in[0];
    const float* dv   = (const float*)d_in[1];
    // d_in[2] = conv_w (dead in reference)
    const float* ctw  = (const float*)d_in[3];
    const float* memW = (const float*)d_in[4];
    const float* dW   = (const float*)d_in[5];
    const float* fcw  = (const float*)d_in[6];
    const float* fcwb = (const float*)d_in[7];
    const float* fcb  = (const float*)d_in[8];
    const float* fcbb = (const float*)d_in[9];
    float* out = (float*)d_out;

    int Bn = in_sizes[0] / LREF;

    cudaFuncSetAttribute(k_main, cudaFuncAttributeMaxDynamicSharedMemorySize, SMEM_SZ);

    k_wconv<<<(LREF * KPAD + 255) / 256, 256>>>(memW, ctw);
    k_att<<<Bn / 256, 256>>>(dv, dW);
    k_main<<<Bn / 128, 256, SMEM_SZ>>>(x, fcw, fcwb, fcb, fcbb, out, Bn);
}

// round 8
// speedup vs baseline: 1.6119x; 1.0328x over previous
#include <cuda_runtime.h>
#include <cuda_bf16.h>
#include <cstdint>

#define LREF  1024
#define FEA   1028
#define MEMD  50
#define KPAD  64
#define DATED 32
#define MAXB  32768

// ------------------- device scratch (allocation-free rule) -------------------
__device__ __nv_bfloat16 g_atth[MAXB * KPAD];   // att hi  [row][k] padded
__device__ __nv_bfloat16 g_attl[MAXB * KPAD];   // att lo
__device__ __nv_bfloat16 g_Bh[LREF * KPAD];     // Wfold^T hi [col][k]
__device__ __nv_bfloat16 g_Bl[LREF * KPAD];     // Wfold^T lo

// ------------------- helpers -------------------
__device__ __forceinline__ uint32_t smem_u32(const void* p) {
    uint32_t a;
    asm("{ .reg .u64 t; cvta.to.shared.u64 t, %1; cvt.u32.u64 %0, t; }" : "=r"(a) : "l"(p));
    return a;
}
__device__ __forceinline__ void ldsm_x4(uint32_t* r, uint32_t a) {
    asm volatile("ldmatrix.sync.aligned.m8n8.x4.shared.b16 {%0,%1,%2,%3}, [%4];"
                 : "=r"(r[0]), "=r"(r[1]), "=r"(r[2]), "=r"(r[3]) : "r"(a));
}
__device__ __forceinline__ void mma_bf16(float* d, const uint32_t* a, const uint32_t* b) {
    asm volatile(
        "mma.sync.aligned.m16n8k16.row.col.f32.bf16.bf16.f32 "
        "{%0,%1,%2,%3}, {%4,%5,%6,%7}, {%8,%9}, {%0,%1,%2,%3};"
        : "+f"(d[0]), "+f"(d[1]), "+f"(d[2]), "+f"(d[3])
        : "r"(a[0]), "r"(a[1]), "r"(a[2]), "r"(a[3]), "r"(b[0]), "r"(b[1]));
}
__device__ __forceinline__ void cp16(uint32_t dst, const void* src) {
    asm volatile("cp.async.cg.shared.global [%0], [%1], 16;" :: "r"(dst), "l"(src) : "memory");
}
#define CP_COMMIT() asm volatile("cp.async.commit_group;" ::: "memory")
#define CP_WAIT(n)  asm volatile("cp.async.wait_group %0;" :: "n"(n) : "memory")

// XOR swizzle for 128B-row tiles: conflict-free ldmatrix + conflict-free stores
__device__ __forceinline__ uint32_t swz(uint32_t r, uint32_t c) {
    return r * 128u + (c ^ ((r & 7u) << 4));
}

// smem layout (bytes)
#define OFF_FCW 0
#define OFF_FCB 4096
#define OFF_WT  8192
#define OFF_BS  8704
#define OFF_A   9216                    // hi 16KB + lo 16KB
#define OFF_B   41984                   // 2 bufs x (hi 16KB + lo 16KB)
#define SMEM_SZ (OFF_B + 65536)         // 107520 -> occ 2

// ---------------------------------------------------------------------------
// k_prep: blocks [0,256) fold conv into Wfold^T (bf16 hi/lo, K padded 50->64);
//         blocks [256,...) compute att -> bf16 hi/lo padded
// ---------------------------------------------------------------------------
__global__ __launch_bounds__(256) void k_prep(const float* __restrict__ mem_W,
                                              const float* __restrict__ convt_w,
                                              const float* __restrict__ dv,
                                              const float* __restrict__ dW) {
    __shared__ float s_dv[256][DATED + 1];
    __shared__ float s_dW[MEMD][DATED];
    __shared__ float s_out[256][MEMD + 1];

    int t = threadIdx.x;

    if (blockIdx.x < 256) {
        int i = blockIdx.x * 256 + t;
        int c = i >> 6, k = i & 63;
        float s = 0.f;
        if (k < MEMD) {
            float w0 = convt_w[4], w1 = convt_w[3], w2 = convt_w[2], w3 = convt_w[1], w4 = convt_w[0];
            const float* p = mem_W + k * FEA + c;
            s = p[0]*w0 + p[1]*w1 + p[2]*w2 + p[3]*w3 + p[4]*w4;
        }
        __nv_bfloat16 h = __float2bfloat16_rn(s);
        __nv_bfloat16 l = __float2bfloat16_rn(s - __bfloat162float(h));
        g_Bh[i] = h;
        g_Bl[i] = l;
        return;
    }

    int base = (blockIdx.x - 256) * 256;

    for (int i = t; i < MEMD * DATED; i += 256) s_dW[i / DATED][i % DATED] = dW[i];
    for (int i = t; i < 256 * DATED; i += 256)
        s_dv[i / DATED][i % DATED] = dv[(size_t)base * DATED + i];
    __syncthreads();

    float sc[MEMD];
    float mx = -1e30f;
    #pragma unroll
    for (int m = 0; m < MEMD; m++) {
        float s = 0.f;
        #pragma unroll
        for (int d = 0; d < DATED; d++) s += s_dv[t][d] * s_dW[m][d];
        sc[m] = s;
        mx = fmaxf(mx, s);
    }
    float se = 0.f;
    #pragma unroll
    for (int m = 0; m < MEMD; m++) { float e = __expf(sc[m] - mx); sc[m] = e; se += e; }
    float inv = 1.f / se;
    float s2 = 0.f;
    #pragma unroll
    for (int m = 0; m < MEMD; m++) {
        float a = sc[m] * inv;
        float d = a - 0.0025f;
        float v = fmaxf(d, 0.f) * a / (fabsf(d) + 1e-12f);
        sc[m] = v;
        s2 += fabsf(v);
    }
    float inv2 = 1.f / (s2 + 1e-12f);
    #pragma unroll
    for (int m = 0; m < MEMD; m++) s_out[t][m] = sc[m] * inv2;
    __syncthreads();

    for (int i = t; i < 256 * KPAD; i += 256) {
        int r = i >> 6, k = i & 63;
        float a = (k < MEMD) ? s_out[r][k] : 0.f;
        __nv_bfloat16 h = __float2bfloat16_rn(a);
        __nv_bfloat16 l = __float2bfloat16_rn(a - __bfloat162float(h));
        size_t gi = (size_t)base * KPAD + i;
        g_atth[gi] = h;
        g_attl[gi] = l;
    }
}

// ---------------------------------------------------------------------------
// stage one B col-block (hi+lo, 32KB) into smem buffer via cp.async
// ---------------------------------------------------------------------------
__device__ __forceinline__ void stage_B(uint32_t sb, int cb, int buf, int t) {
    #pragma unroll
    for (int j = 0; j < 8; j++) {
        int i = t + j * 256;
        int term = i >> 10, rem = i & 1023, r = rem >> 3, ch = rem & 7;
        const __nv_bfloat16* src = (term ? g_Bl : g_Bh) + (size_t)(cb * 128 + r) * KPAD + ch * 8;
        cp16(sb + OFF_B + buf * 32768 + term * 16384 + swz((uint32_t)r, (uint32_t)(ch * 16)), src);
    }
}

// ---------------------------------------------------------------------------
// k_main: CTA = 128 rows. cp.async-pipelined bf16 3-term mma.sync GEMM with
//         fused tanh gates + epilogue.
// ---------------------------------------------------------------------------
__global__ __launch_bounds__(256, 2) void k_main(const float* __restrict__ x,
                                                 const float* __restrict__ fcw,
                                                 const float* __restrict__ fcwb,
                                                 const float* __restrict__ fcb,
                                                 const float* __restrict__ fcbb,
                                                 float* __restrict__ out, int Bn) {
    extern __shared__ char smem[];
    const uint32_t sb = smem_u32(smem);
    const int t = threadIdx.x;
    const int warp = t >> 5, lane = t & 31;
    const int rowBase = blockIdx.x * 128;

    float* s_fcw = (float*)(smem + OFF_FCW);
    float* s_fcb = (float*)(smem + OFF_FCB);
    float* s_wt  = (float*)(smem + OFF_WT);
    float* s_bs  = (float*)(smem + OFF_BS);

    // group 0: A (att) tiles + fc weights
    #pragma unroll
    for (int j = 0; j < 8; j++) {
        int i = t + j * 256;
        int term = i >> 10, rem = i & 1023, r = rem >> 3, ch = rem & 7;
        const __nv_bfloat16* src = (term ? g_attl : g_atth) + (size_t)(rowBase + r) * KPAD + ch * 8;
        cp16(sb + OFF_A + term * 16384 + swz((uint32_t)r, (uint32_t)(ch * 16)), src);
    }
    cp16(sb + OFF_FCW + t * 16, fcw + t * 4);
    cp16(sb + OFF_FCB + t * 16, fcb + t * 4);
    CP_COMMIT();
    // groups 1,2: first two B col-blocks
    stage_B(sb, 0, 0, t); CP_COMMIT();
    stage_B(sb, 1, 1, t); CP_COMMIT();

    CP_WAIT(2);          // group 0 (A + fc) done
    __syncthreads();

    // ---- A fragments into registers (once) ----
    uint32_t ah[4][4], al[4][4];
    {
        uint32_t ra = (uint32_t)(warp * 16 + (lane & 15));
        uint32_t cbase = (uint32_t)((lane >> 4) * 16);
        #pragma unroll
        for (int ks = 0; ks < 4; ks++) {
            uint32_t off = swz(ra, cbase + ks * 32);
            ldsm_x4(ah[ks], sb + OFF_A + off);
            ldsm_x4(al[ks], sb + OFF_A + 16384 + off);
        }
    }

    // ---- phase A: per-row tanh gates (8 warps x 16 rows); B copies in flight ----
    {
        float fwb = fcwb[0], fbb = fcbb[0];
        for (int rr = 0; rr < 16; rr++) {
            int r = warp * 16 + rr;
            const float4* xr  = (const float4*)(x + (size_t)(rowBase + r) * LREF);
            const float4* fw4 = (const float4*)s_fcw;
            const float4* fb4 = (const float4*)s_fcb;
            float dw = 0.f, db = 0.f;
            #pragma unroll
            for (int j = 0; j < 8; j++) {
                float4 v = xr[lane + 32 * j];
                float4 a = fw4[lane + 32 * j];
                float4 b = fb4[lane + 32 * j];
                dw += v.x*a.x + v.y*a.y + v.z*a.z + v.w*a.w;
                db += v.x*b.x + v.y*b.y + v.z*b.z + v.w*b.w;
            }
            #pragma unroll
            for (int o = 16; o; o >>= 1) {
                dw += __shfl_xor_sync(0xffffffffu, dw, o);
                db += __shfl_xor_sync(0xffffffffu, db, o);
            }
            if (lane == 0) {
                float wt = tanhf(dw + fwb) * 0.5f + 1.0f;
                float bs = tanhf(db + fbb) * 0.5f;
                s_wt[r] = wt;
                s_bs[r] = bs;
                out[(size_t)Bn * LREF + rowBase + r]      = wt;
                out[(size_t)Bn * LREF + Bn + rowBase + r] = bs;
            }
        }
    }
    __syncwarp();

    // per-thread epilogue coords (warp-local rows -> no block barrier needed)
    const int grp = lane >> 2, qc = lane & 3;
    const float wt0 = s_wt[warp * 16 + grp],     bs0 = s_bs[warp * 16 + grp];
    const float wt1 = s_wt[warp * 16 + grp + 8], bs1 = s_bs[warp * 16 + grp + 8];

    // B-fragment per-lane constants (x4 = two n8 blocks at once)
    const uint32_t rb  = (uint32_t)((lane & 7) + ((lane >> 4) << 3));
    const uint32_t ccb = (uint32_t)(((lane >> 3) & 1) * 16);
    const uint32_t xv  = (uint32_t)((lane & 7) << 4);

    // ---- GEMM over 8 col-blocks, double-buffered cp.async ----
    for (int cb = 0; cb < 8; cb++) {
        CP_WAIT(1);          // B(cb) arrived (own copies)
        __syncthreads();     // visible to all; buf not yet being overwritten
        const uint32_t bbase = sb + OFF_B + (uint32_t)((cb & 1) * 32768);

        float acc[16][4];
        #pragma unroll
        for (int nt = 0; nt < 16; nt++) {
            acc[nt][0] = 0.f; acc[nt][1] = 0.f; acc[nt][2] = 0.f; acc[nt][3] = 0.f;
        }

        #pragma unroll
        for (int ks = 0; ks < 4; ks++) {
            const uint32_t col = (ccb + (uint32_t)(ks * 32)) ^ xv;
            #pragma unroll
            for (int ntp = 0; ntp < 8; ntp++) {
                uint32_t addr = bbase + (uint32_t)((ntp * 16) + rb) * 128u + col;
                uint32_t bh[4], bl[4];
                ldsm_x4(bh, addr);
                ldsm_x4(bl, addr + 16384);
                mma_bf16(acc[2*ntp],     ah[ks], bh);
                mma_bf16(acc[2*ntp + 1], ah[ks], bh + 2);
                mma_bf16(acc[2*ntp],     al[ks], bh);
                mma_bf16(acc[2*ntp + 1], al[ks], bh + 2);
                mma_bf16(acc[2*ntp],     ah[ks], bl);
                mma_bf16(acc[2*ntp + 1], ah[ks], bl + 2);
            }
        }

        // fused epilogue: out = acc*wt + bs (4 lanes -> 32B contiguous per row)
        {
            size_t r0 = (size_t)(rowBase + warp * 16 + grp) * LREF;
            size_t r1 = r0 + 8 * LREF;
            int colBase = cb * 128 + qc * 2;
            #pragma unroll
            for (int nt = 0; nt < 16; nt++) {
                int col = colBase + nt * 8;
                *(float2*)&out[r0 + col] =
                    make_float2(acc[nt][0] * wt0 + bs0, acc[nt][1] * wt0 + bs0);
                *(float2*)&out[r1 + col] =
                    make_float2(acc[nt][2] * wt1 + bs1, acc[nt][3] * wt1 + bs1);
            }
        }

        __syncthreads();                       // all readers done with buf(cb)
        if (cb + 2 < 8) stage_B(sb, cb + 2, cb & 1, t);
        CP_COMMIT();                           // commit (possibly empty) group
    }
}

// ---------------------------------------------------------------------------
extern "C" void kernel_launch(void* const* d_in, const int* in_sizes, int n_in,
                              void* d_out, int out_size) {
    const float* x    = (const float*)d_in[0];
    const float* dv   = (const float*)d_in[1];
    // d_in[2] = conv_w (dead in reference)
    const float* ctw  = (const float*)d_in[3];
    const float* memW = (const float*)d_in[4];
    const float* dW   = (const float*)d_in[5];
    const float* fcw  = (const float*)d_in[6];
    const float* fcwb = (const float*)d_in[7];
    const float* fcb  = (const float*)d_in[8];
    const float* fcbb = (const float*)d_in[9];
    float* out = (float*)d_out;

    int Bn = in_sizes[0] / LREF;

    cudaFuncSetAttribute(k_main, cudaFuncAttributeMaxDynamicSharedMemorySize, SMEM_SZ);

    k_prep<<<256 + Bn / 256, 256>>>(memW, ctw, dv, dW);
    k_main<<<Bn / 128, 256, SMEM_SZ>>>(x, fcw, fcwb, fcb, fcbb, out, Bn);
}

// round 9
// speedup vs baseline: 1.8077x; 1.1215x over previous
#include <cuda_runtime.h>
#include <cuda_bf16.h>
#include <cstdint>

#define LREF  1024
#define FEA   1028
#define MEMD  50
#define KPAD  64
#define DATED 32
#define MAXB  32768

// ------------------- device scratch (allocation-free rule) -------------------
__device__ __nv_bfloat16 g_atth[MAXB * KPAD];   // att hi  [row][k] padded
__device__ __nv_bfloat16 g_attl[MAXB * KPAD];   // att lo
__device__ __nv_bfloat16 g_Bh[LREF * KPAD];     // Wfold^T hi [col][k]
__device__ __nv_bfloat16 g_Bl[LREF * KPAD];     // Wfold^T lo
__device__ float         g_wt[MAXB];            // gate weight per row
__device__ float         g_bs[MAXB];            // gate bias   per row

// ------------------- helpers -------------------
__device__ __forceinline__ uint32_t smem_u32(const void* p) {
    uint32_t a;
    asm("{ .reg .u64 t; cvta.to.shared.u64 t, %1; cvt.u32.u64 %0, t; }" : "=r"(a) : "l"(p));
    return a;
}
__device__ __forceinline__ void ldsm_x4(uint32_t* r, uint32_t a) {
    asm volatile("ldmatrix.sync.aligned.m8n8.x4.shared.b16 {%0,%1,%2,%3}, [%4];"
                 : "=r"(r[0]), "=r"(r[1]), "=r"(r[2]), "=r"(r[3]) : "r"(a));
}
__device__ __forceinline__ void mma_bf16(float* d, const uint32_t* a, const uint32_t* b) {
    asm volatile(
        "mma.sync.aligned.m16n8k16.row.col.f32.bf16.bf16.f32 "
        "{%0,%1,%2,%3}, {%4,%5,%6,%7}, {%8,%9}, {%0,%1,%2,%3};"
        : "+f"(d[0]), "+f"(d[1]), "+f"(d[2]), "+f"(d[3])
        : "r"(a[0]), "r"(a[1]), "r"(a[2]), "r"(a[3]), "r"(b[0]), "r"(b[1]));
}
__device__ __forceinline__ void cp16(uint32_t dst, const void* src) {
    asm volatile("cp.async.cg.shared.global [%0], [%1], 16;" :: "r"(dst), "l"(src) : "memory");
}
#define CP_COMMIT() asm volatile("cp.async.commit_group;" ::: "memory")
#define CP_WAIT(n)  asm volatile("cp.async.wait_group %0;" :: "n"(n) : "memory")

// XOR swizzle for 128B-row tiles: conflict-free ldmatrix + conflict-free stores
__device__ __forceinline__ uint32_t swz(uint32_t r, uint32_t c) {
    return r * 128u + (c ^ ((r & 7u) << 4));
}

// k_main smem layout (bytes)
#define OFF_WT  0                       // 512B
#define OFF_BS  512                     // 512B
#define OFF_A   1024                    // hi 16KB + lo 16KB
#define OFF_B   33792                   // 2 bufs x (hi 16KB + lo 16KB)
#define SMEM_SZ (OFF_B + 65536)         // 99328 -> occ 2

// ---------------------------------------------------------------------------
// k_prep: three block ranges (gates first = the 128MB long pole):
//   [0, Bn/64)               : tanh gates -> g_wt/g_bs + out tail
//   [Bn/64, Bn/64+Bn/256)    : att -> bf16 hi/lo padded
//   [.., +256)               : fold conv into Wfold^T bf16 hi/lo
// ---------------------------------------------------------------------------
__global__ __launch_bounds__(256) void k_prep(const float* __restrict__ x,
                                              const float* __restrict__ fcw,
                                              const float* __restrict__ fcwb,
                                              const float* __restrict__ fcb,
                                              const float* __restrict__ fcbb,
                                              float* __restrict__ out,
                                              const float* __restrict__ mem_W,
                                              const float* __restrict__ convt_w,
                                              const float* __restrict__ dv,
                                              const float* __restrict__ dW, int Bn) {
    int t = threadIdx.x;
    int warp = t >> 5, lane = t & 31;
    const int gatesBlocks = Bn / 64;
    const int attBlocks   = Bn / 256;

    if ((int)blockIdx.x < gatesBlocks) {
        // ---------------- gates: 64 rows per block, 8 rows per warp ----------------
        __shared__ float s_fcw[LREF];
        __shared__ float s_fcb[LREF];
        for (int i = t; i < LREF / 4; i += 256) {
            ((float4*)s_fcw)[i] = ((const float4*)fcw)[i];
            ((float4*)s_fcb)[i] = ((const float4*)fcb)[i];
        }
        __syncthreads();

        int rowBase = blockIdx.x * 64;
        float fwb = fcwb[0], fbb = fcbb[0];
        for (int rr = 0; rr < 8; rr++) {
            int r = warp * 8 + rr;
            const float4* xr  = (const float4*)(x + (size_t)(rowBase + r) * LREF);
            const float4* fw4 = (const float4*)s_fcw;
            const float4* fb4 = (const float4*)s_fcb;
            float dw = 0.f, db = 0.f;
            #pragma unroll
            for (int j = 0; j < 8; j++) {
                float4 v = xr[lane + 32 * j];
                float4 a = fw4[lane + 32 * j];
                float4 b = fb4[lane + 32 * j];
                dw += v.x*a.x + v.y*a.y + v.z*a.z + v.w*a.w;
                db += v.x*b.x + v.y*b.y + v.z*b.z + v.w*b.w;
            }
            #pragma unroll
            for (int o = 16; o; o >>= 1) {
                dw += __shfl_xor_sync(0xffffffffu, dw, o);
                db += __shfl_xor_sync(0xffffffffu, db, o);
            }
            if (lane == 0) {
                float wt = tanhf(dw + fwb) * 0.5f + 1.0f;
                float bs = tanhf(db + fbb) * 0.5f;
                int row = rowBase + r;
                g_wt[row] = wt;
                g_bs[row] = bs;
                out[(size_t)Bn * LREF + row]      = wt;
                out[(size_t)Bn * LREF + Bn + row] = bs;
            }
        }
        return;
    }

    if ((int)blockIdx.x < gatesBlocks + attBlocks) {
        // ---------------- att ----------------
        __shared__ float s_dv[256][DATED + 1];
        __shared__ float s_dW[MEMD][DATED];
        __shared__ float s_out[256][MEMD + 1];

        int base = (blockIdx.x - gatesBlocks) * 256;

        for (int i = t; i < MEMD * DATED; i += 256) s_dW[i / DATED][i % DATED] = dW[i];
        for (int i = t; i < 256 * DATED; i += 256)
            s_dv[i / DATED][i % DATED] = dv[(size_t)base * DATED + i];
        __syncthreads();

        float sc[MEMD];
        float mx = -1e30f;
        #pragma unroll
        for (int m = 0; m < MEMD; m++) {
            float s = 0.f;
            #pragma unroll
            for (int d = 0; d < DATED; d++) s += s_dv[t][d] * s_dW[m][d];
            sc[m] = s;
            mx = fmaxf(mx, s);
        }
        float se = 0.f;
        #pragma unroll
        for (int m = 0; m < MEMD; m++) { float e = __expf(sc[m] - mx); sc[m] = e; se += e; }
        float inv = 1.f / se;
        float s2 = 0.f;
        #pragma unroll
        for (int m = 0; m < MEMD; m++) {
            float a = sc[m] * inv;
            float d = a - 0.0025f;
            float v = fmaxf(d, 0.f) * a / (fabsf(d) + 1e-12f);
            sc[m] = v;
            s2 += fabsf(v);
        }
        float inv2 = 1.f / (s2 + 1e-12f);
        #pragma unroll
        for (int m = 0; m < MEMD; m++) s_out[t][m] = sc[m] * inv2;
        __syncthreads();

        for (int i = t; i < 256 * KPAD; i += 256) {
            int r = i >> 6, k = i & 63;
            float a = (k < MEMD) ? s_out[r][k] : 0.f;
            __nv_bfloat16 h = __float2bfloat16_rn(a);
            __nv_bfloat16 l = __float2bfloat16_rn(a - __bfloat162float(h));
            size_t gi = (size_t)base * KPAD + i;
            g_atth[gi] = h;
            g_attl[gi] = l;
        }
        return;
    }

    // ---------------- wconv ----------------
    {
        int i = (blockIdx.x - gatesBlocks - attBlocks) * 256 + t;
        int c = i >> 6, k = i & 63;
        float s = 0.f;
        if (k < MEMD) {
            float w0 = convt_w[4], w1 = convt_w[3], w2 = convt_w[2], w3 = convt_w[1], w4 = convt_w[0];
            const float* p = mem_W + k * FEA + c;
            s = p[0]*w0 + p[1]*w1 + p[2]*w2 + p[3]*w3 + p[4]*w4;
        }
        __nv_bfloat16 h = __float2bfloat16_rn(s);
        __nv_bfloat16 l = __float2bfloat16_rn(s - __bfloat162float(h));
        g_Bh[i] = h;
        g_Bl[i] = l;
    }
}

// ---------------------------------------------------------------------------
// stage one B col-block (hi+lo, 32KB) into smem buffer via cp.async
// ---------------------------------------------------------------------------
__device__ __forceinline__ void stage_B(uint32_t sb, int cb, int buf, int t) {
    #pragma unroll
    for (int j = 0; j < 8; j++) {
        int i = t + j * 256;
        int term = i >> 10, rem = i & 1023, r = rem >> 3, ch = rem & 7;
        const __nv_bfloat16* src = (term ? g_Bl : g_Bh) + (size_t)(cb * 128 + r) * KPAD + ch * 8;
        cp16(sb + OFF_B + buf * 32768 + term * 16384 + swz((uint32_t)r, (uint32_t)(ch * 16)), src);
    }
}

// ---------------------------------------------------------------------------
// k_main: pure GEMM + fused gate epilogue. CTA = 128 rows, 256 threads.
// ---------------------------------------------------------------------------
__global__ __launch_bounds__(256, 2) void k_main(float* __restrict__ out, int Bn) {
    extern __shared__ char smem[];
    const uint32_t sb = smem_u32(smem);
    const int t = threadIdx.x;
    const int warp = t >> 5, lane = t & 31;
    const int rowBase = blockIdx.x * 128;

    float* s_wt = (float*)(smem + OFF_WT);
    float* s_bs = (float*)(smem + OFF_BS);

    // group 0: A (att) tiles + gates
    #pragma unroll
    for (int j = 0; j < 8; j++) {
        int i = t + j * 256;
        int term = i >> 10, rem = i & 1023, r = rem >> 3, ch = rem & 7;
        const __nv_bfloat16* src = (term ? g_attl : g_atth) + (size_t)(rowBase + r) * KPAD + ch * 8;
        cp16(sb + OFF_A + term * 16384 + swz((uint32_t)r, (uint32_t)(ch * 16)), src);
    }
    if (t < 32)              cp16(sb + OFF_WT + t * 16, g_wt + rowBase + t * 4);
    else if (t < 64)         cp16(sb + OFF_BS + (t - 32) * 16, g_bs + rowBase + (t - 32) * 4);
    CP_COMMIT();
    // groups 1,2: first two B col-blocks
    stage_B(sb, 0, 0, t); CP_COMMIT();
    stage_B(sb, 1, 1, t); CP_COMMIT();

    CP_WAIT(2);          // group 0 done
    __syncthreads();

    // ---- A fragments into registers (once) ----
    uint32_t ah[4][4], al[4][4];
    {
        uint32_t ra = (uint32_t)(warp * 16 + (lane & 15));
        uint32_t cbase = (uint32_t)((lane >> 4) * 16);
        #pragma unroll
        for (int ks = 0; ks < 4; ks++) {
            uint32_t off = swz(ra, cbase + ks * 32);
            ldsm_x4(ah[ks], sb + OFF_A + off);
            ldsm_x4(al[ks], sb + OFF_A + 16384 + off);
        }
    }

    // per-thread epilogue coords
    const int grp = lane >> 2, qc = lane & 3;
    const float wt0 = s_wt[warp * 16 + grp],     bs0 = s_bs[warp * 16 + grp];
    const float wt1 = s_wt[warp * 16 + grp + 8], bs1 = s_bs[warp * 16 + grp + 8];

    // B-fragment per-lane constants (x4 = two n8 blocks at once)
    const uint32_t rb  = (uint32_t)((lane & 7) + ((lane >> 4) << 3));
    const uint32_t ccb = (uint32_t)(((lane >> 3) & 1) * 16);
    const uint32_t xv  = (uint32_t)((lane & 7) << 4);

    // ---- GEMM over 8 col-blocks, double-buffered cp.async ----
    for (int cb = 0; cb < 8; cb++) {
        CP_WAIT(1);          // B(cb) arrived
        __syncthreads();
        const uint32_t bbase = sb + OFF_B + (uint32_t)((cb & 1) * 32768);

        float acc[16][4];
        #pragma unroll
        for (int nt = 0; nt < 16; nt++) {
            acc[nt][0] = 0.f; acc[nt][1] = 0.f; acc[nt][2] = 0.f; acc[nt][3] = 0.f;
        }

        #pragma unroll
        for (int ks = 0; ks < 4; ks++) {
            const uint32_t col = (ccb + (uint32_t)(ks * 32)) ^ xv;
            #pragma unroll
            for (int ntp = 0; ntp < 8; ntp++) {
                uint32_t addr = bbase + (uint32_t)((ntp * 16) + rb) * 128u + col;
                uint32_t bh[4], bl[4];
                ldsm_x4(bh, addr);
                ldsm_x4(bl, addr + 16384);
                mma_bf16(acc[2*ntp],     ah[ks], bh);
                mma_bf16(acc[2*ntp + 1], ah[ks], bh + 2);
                mma_bf16(acc[2*ntp],     al[ks], bh);
                mma_bf16(acc[2*ntp + 1], al[ks], bh + 2);
                mma_bf16(acc[2*ntp],     ah[ks], bl);
                mma_bf16(acc[2*ntp + 1], ah[ks], bl + 2);
            }
        }

        // fused epilogue: out = acc*wt + bs
        {
            size_t r0 = (size_t)(rowBase + warp * 16 + grp) * LREF;
            size_t r1 = r0 + 8 * LREF;
            int colBase = cb * 128 + qc * 2;
            #pragma unroll
            for (int nt = 0; nt < 16; nt++) {
                int col = colBase + nt * 8;
                *(float2*)&out[r0 + col] =
                    make_float2(acc[nt][0] * wt0 + bs0, acc[nt][1] * wt0 + bs0);
                *(float2*)&out[r1 + col] =
                    make_float2(acc[nt][2] * wt1 + bs1, acc[nt][3] * wt1 + bs1);
            }
        }

        __syncthreads();                       // all readers done with buf(cb)
        if (cb + 2 < 8) stage_B(sb, cb + 2, cb & 1, t);
        CP_COMMIT();                           // commit (possibly empty) group
    }
}

// ---------------------------------------------------------------------------
extern "C" void kernel_launch(void* const* d_in, const int* in_sizes, int n_in,
                              void* d_out, int out_size) {
    const float* x    = (const float*)d_in[0];
    const float* dv   = (const float*)d_in[1];
    // d_in[2] = conv_w (dead in reference)
    const float* ctw  = (const float*)d_in[3];
    const float* memW = (const float*)d_in[4];
    const float* dW   = (const float*)d_in[5];
    const float* fcw  = (const float*)d_in[6];
    const float* fcwb = (const float*)d_in[7];
    const float* fcb  = (const float*)d_in[8];
    const float* fcbb = (const float*)d_in[9];
    float* out = (float*)d_out;

    int Bn = in_sizes[0] / LREF;

    cudaFuncSetAttribute(k_main, cudaFuncAttributeMaxDynamicSharedMemorySize, SMEM_SZ);

    int gridPrep = Bn / 64 + Bn / 256 + 256;
    k_prep<<<gridPrep, 256>>>(x, fcw, fcwb, fcb, fcbb, out, memW, ctw, dv, dW, Bn);
    k_main<<<Bn / 128, 256, SMEM_SZ>>>(out, Bn);
}